// round 3
// baseline (speedup 1.0000x reference)
#include <cuda_runtime.h>

#define BATCH 4
#define NINST 32
#define HW (512*512)
#define CHUNK 4096
#define NCHUNK 513                 // covers 2^21+1 bins (bit-pattern bins of e in [0,2])
#define NBALLOC (NCHUNK*CHUNK)     // 2101248 padded bins

// Static scratch (no runtime allocation allowed)
static __device__ unsigned long long g_hist[BATCH][NBALLOC];   // (pos<<32)|neg per bin
static __device__ double             g_sum[BATCH][NINST][4];   // sx, sy, ssig, ssig2
static __device__ unsigned int       g_cnt[BATCH][NINST];
static __device__ float4             g_prm[BATCH][NINST];      // cx, cy, -0.5/sigma^2, 0
static __device__ double             g_var[BATCH];
static __device__ double             g_lov[BATCH];
static __device__ unsigned int       g_P[BATCH];
static __device__ unsigned long long g_chunksum[BATCH][NCHUNK];
static __device__ unsigned long long g_chunkpre[BATCH][NCHUNK];
static __device__ int                g_lab64;    // 1 if labels are int64, 0 if int32

// ---------------------------------------------------------------- dtype sniff
// int64 labels in [0,32]: every odd int32 word (high half) is 0.
// int32 labels: odd words are labels, nonzero w.p. 32/33 each.
__global__ void k_detect(const int* __restrict__ lab32) {
    __shared__ int s_or;
    if (threadIdx.x == 0) s_or = 0;
    __syncthreads();
    int v = lab32[2 * threadIdx.x + 1];   // 256 odd words
    #pragma unroll
    for (int o = 16; o; o >>= 1) v |= __shfl_down_sync(0xffffffffu, v, o);
    if ((threadIdx.x & 31) == 0) atomicOr(&s_or, v);
    __syncthreads();
    if (threadIdx.x == 0) g_lab64 = (s_or == 0) ? 1 : 0;
}

__device__ __forceinline__ int load_lab(const int* __restrict__ lab32, int idx, int f64) {
    return lab32[f64 ? (idx << 1) : idx];
}

// ---------------------------------------------------------------- zero
__global__ void k_zero() {
    size_t stride = (size_t)gridDim.x * blockDim.x;
    size_t i = (size_t)blockIdx.x * blockDim.x + threadIdx.x;
    unsigned long long* h = &g_hist[0][0];
    const size_t n = (size_t)BATCH * NBALLOC;
    for (size_t k = i; k < n; k += stride) h[k] = 0ULL;
    if (i < BATCH * NINST * 4) (&g_sum[0][0][0])[i] = 0.0;
    if (i < BATCH * NINST)     (&g_cnt[0][0])[i] = 0u;
    if (i < BATCH)             { g_var[i] = 0.0; g_lov[i] = 0.0; }
}

// ---------------------------------------------------------------- per-instance stats
__global__ void k_stats(const float* __restrict__ emb,
                        const float* __restrict__ sig,
                        const int* __restrict__ lab32) {
    int b = blockIdx.y;
    int pix = blockIdx.x * blockDim.x + threadIdx.x;
    __shared__ double s_sx[NINST], s_sy[NINST], s_ss[NINST], s_ss2[NINST];
    __shared__ unsigned int s_c[NINST];
    if (threadIdx.x < NINST) {
        s_sx[threadIdx.x] = 0.0; s_sy[threadIdx.x] = 0.0;
        s_ss[threadIdx.x] = 0.0; s_ss2[threadIdx.x] = 0.0;
        s_c[threadIdx.x] = 0u;
    }
    __syncthreads();
    int f64 = g_lab64;
    if (pix < HW) {
        int g = load_lab(lab32, b * HW + pix, f64);
        if (g > 0 && g <= NINST) {
            int n = g - 1;
            float ex = emb[(b * 2 + 0) * HW + pix];
            float ey = emb[(b * 2 + 1) * HW + pix];
            float s  = sig[b * HW + pix];
            atomicAdd(&s_sx[n], (double)ex);
            atomicAdd(&s_sy[n], (double)ey);
            atomicAdd(&s_ss[n], (double)s);
            atomicAdd(&s_ss2[n], (double)s * (double)s);
            atomicAdd(&s_c[n], 1u);
        }
    }
    __syncthreads();
    if (threadIdx.x < NINST) {
        int n = threadIdx.x;
        if (s_c[n]) {
            atomicAdd(&g_sum[b][n][0], s_sx[n]);
            atomicAdd(&g_sum[b][n][1], s_sy[n]);
            atomicAdd(&g_sum[b][n][2], s_ss[n]);
            atomicAdd(&g_sum[b][n][3], s_ss2[n]);
            atomicAdd(&g_cnt[b][n], s_c[n]);
        }
    }
}

// ---------------------------------------------------------------- finalize stats
__global__ void k_finalize() {
    int t = threadIdx.x;              // 128 threads: b = warp, n = lane
    int b = t >> 5, n = t & 31;
    double c  = (double)g_cnt[b][n];
    double ic = (c > 0.0) ? (1.0 / c) : 0.0;
    double cx = g_sum[b][n][0] * ic;
    double cy = g_sum[b][n][1] * ic;
    double m  = g_sum[b][n][2] * ic;
    double vp = g_sum[b][n][3] - c * m * m;   // sum (s - mean)^2 over instance
    float zc = (m > 0.0) ? (float)(-0.5 / (m * m)) : 0.f;
    g_prm[b][n] = make_float4((float)cx, (float)cy, zc, 0.f);
    unsigned cc = g_cnt[b][n];
    double icsum = ic;
    #pragma unroll
    for (int o = 16; o; o >>= 1) {
        vp    += __shfl_down_sync(0xffffffffu, vp, o);
        icsum += __shfl_down_sync(0xffffffffu, icsum, o);
        cc    += __shfl_down_sync(0xffffffffu, cc, o);
    }
    if (n == 0) {
        g_var[b] = vp * icsum / (double)NINST;  // mean_n (S / c_n)
        g_P[b]   = cc;                          // total positives
    }
}

// ---------------------------------------------------------------- main: errors -> histogram
__global__ void k_main(const float* __restrict__ emb,
                       const int* __restrict__ lab32) {
    int b = blockIdx.y;
    __shared__ float4 sp[NINST];
    if (threadIdx.x < NINST) sp[threadIdx.x] = g_prm[b][threadIdx.x];
    __syncthreads();
    int pix = blockIdx.x * blockDim.x + threadIdx.x;
    if (pix >= HW) return;
    int f64 = g_lab64;
    float ex = emb[(b * 2 + 0) * HW + pix];
    float ey = emb[(b * 2 + 1) * HW + pix];
    int g = load_lab(lab32, b * HW + pix, f64);
    unsigned long long* hb = g_hist[b];
    #pragma unroll 8
    for (int n = 0; n < NINST; n++) {
        float4 P = sp[n];
        float dx = P.x - ex;
        float dy = P.y - ey;
        float d2 = fmaf(dx, dx, dy * dy);
        float p  = __expf(d2 * P.z);              // exp(-0.5*(d/sigma)^2)
        bool pos = (g == n + 1);
        float e  = pos ? (2.0f - 2.0f * p) : (2.0f * p);   // hinge error, in [0,2]
        unsigned bin = __float_as_uint(e) >> 9;   // monotone log-spaced binning
        if (bin >= NBALLOC) bin = NBALLOC - 1;    // safety clamp (NaN/garbage)
        atomicAdd(&hb[bin], pos ? (1ULL << 32) : 1ULL);
    }
}

// ---------------------------------------------------------------- chunk sums
__global__ void k_chunksum() {
    int b = blockIdx.y, c = blockIdx.x;
    const unsigned long long* hb = g_hist[b] + (size_t)c * CHUNK;
    unsigned long long acc = 0;
    for (int i = threadIdx.x; i < CHUNK; i += blockDim.x) acc += hb[i];
    __shared__ unsigned long long ss[256];
    ss[threadIdx.x] = acc; __syncthreads();
    for (int o = 128; o; o >>= 1) {
        if (threadIdx.x < o) ss[threadIdx.x] += ss[threadIdx.x + o];
        __syncthreads();
    }
    if (threadIdx.x == 0) g_chunksum[b][c] = ss[0];
}

// ---------------------------------------------------------------- exclusive scan over chunks (descending e)
__global__ void k_scan() {
    int b = blockIdx.x;
    int t = threadIdx.x;               // 1024 threads, NCHUNK=513 entries reversed
    __shared__ unsigned long long ss[1024];
    unsigned long long v = (t < NCHUNK) ? g_chunksum[b][NCHUNK - 1 - t] : 0ULL;
    ss[t] = v; __syncthreads();
    for (int o = 1; o < 1024; o <<= 1) {
        unsigned long long u = (t >= o) ? ss[t - o] : 0ULL;
        __syncthreads();
        ss[t] += u;
        __syncthreads();
    }
    if (t < NCHUNK) g_chunkpre[b][NCHUNK - 1 - t] = ss[t] - v;  // counts strictly above chunk
}

// ---------------------------------------------------------------- per-bin Lovasz contributions
__global__ void k_loss() {
    const int SEG = CHUNK / 256;   // 16 bins per thread, descending order
    int b = blockIdx.y, c = blockIdx.x;
    int t = threadIdx.x;
    int top = c * CHUNK + CHUNK - t * SEG;   // exclusive top bin of this thread's segment
    const unsigned long long* hb = g_hist[b];
    unsigned long long vals[SEG];
    unsigned long long segsum = 0;
    #pragma unroll
    for (int k = 0; k < SEG; k++) { vals[k] = hb[top - 1 - k]; segsum += vals[k]; }

    __shared__ unsigned long long ss[256];
    ss[t] = segsum; __syncthreads();
    #pragma unroll
    for (int o = 1; o < 256; o <<= 1) {
        unsigned long long u = (t >= o) ? ss[t - o] : 0ULL;
        __syncthreads();
        ss[t] += u;
        __syncthreads();
    }
    unsigned long long pref = g_chunkpre[b][c] + (ss[t] - segsum);
    unsigned pp = (unsigned)(pref >> 32);          // positives above
    unsigned nn = (unsigned)(pref & 0xffffffffu);  // negatives above
    unsigned P  = g_P[b];
    float contrib = 0.f;
    #pragma unroll
    for (int k = 0; k < SEG; k++) {
        unsigned long long v = vals[k];
        if (v) {
            unsigned a  = (unsigned)(v >> 32);
            unsigned gn = (unsigned)v;
            unsigned bin = (unsigned)(top - 1 - k);
            float e = __uint_as_float((bin << 9) + 256u);  // bin-center representative
            e = fminf(e, 2.0f);
            // cancellation-free delta-Jaccard: (A*g + a*U1) / (U1*U2)
            float A   = (float)(P - pp);
            float U1  = (float)(P + nn);
            float U2  = U1 + (float)gn;
            float num = A * (float)gn + (float)a * U1;
            contrib += e * num / (U1 * U2);
            pp += a; nn += gn;
        }
    }
    __shared__ float sc[256];
    sc[t] = contrib; __syncthreads();
    for (int o = 128; o; o >>= 1) {
        if (t < o) sc[t] += sc[t + o];
        __syncthreads();
    }
    if (t == 0) atomicAdd(&g_lov[b], (double)sc[0]);
}

// ---------------------------------------------------------------- final mean
__global__ void k_final(float* __restrict__ out) {
    double acc = 0.0;
    #pragma unroll
    for (int b = 0; b < BATCH; b++) acc += g_lov[b] + g_var[b];
    out[0] = (float)(acc / (double)BATCH);
}

extern "C" void kernel_launch(void* const* d_in, const int* in_sizes, int n_in,
                              void* d_out, int out_size) {
    const float* emb   = (const float*)d_in[0];    // [4,2,512,512] f32
    const float* sig   = (const float*)d_in[1];    // [4,1,512,512] f32
    const int* lab32   = (const int*)d_in[2];      // [4,1,512,512] int32 or int64 (sniffed)
    float* out = (float*)d_out;
    (void)in_sizes; (void)n_in; (void)out_size;

    k_detect<<<1, 256>>>(lab32);
    k_zero<<<2048, 1024>>>();
    dim3 gs(HW / 256, BATCH);
    k_stats<<<gs, 256>>>(emb, sig, lab32);
    k_finalize<<<1, 128>>>();
    k_main<<<gs, 256>>>(emb, lab32);
    dim3 gc(NCHUNK, BATCH);
    k_chunksum<<<gc, 256>>>();
    k_scan<<<BATCH, 1024>>>();
    k_loss<<<gc, 256>>>();
    k_final<<<1, 1>>>(out);
}

// round 4
// speedup vs baseline: 1.3544x; 1.3544x over previous
#include <cuda_runtime.h>

#define BATCH 4
#define NINST 32
#define HW (512*512)

// t-histogram: linear bins on t_scaled = (0.5*d^2/sigma^2)*2^14, 32-bit neg counts
#define NBT (1<<20)                // covers t in [0,64): e down to 2*exp(-64)
#define T_INV 6.103515625e-05f     // 2^-14

// e-histogram: float-bit bins of e in [0,2], >>10 (rel width 1.2e-4), packed pos<<32|neg
#define CHUNK 4096
#define NCHUNK 257
#define NBE (NCHUNK*CHUNK)         // 1052672 >= (0x40000000>>10)+1 = 1048577
#define EB_MAX 1048576u

typedef unsigned long long ull;

static __device__ unsigned int g_thist[BATCH][NBT];
static __device__ ull          g_hist[BATCH][NBE];
static __device__ double       g_sum[BATCH][NINST][4];   // sx, sy, ssig, ssig2
static __device__ unsigned int g_cnt[BATCH][NINST];
static __device__ float4       g_prm[BATCH][NINST];      // Bx, By, A, C  (scaled by 2^14)
static __device__ ull          g_prm2[BATCH][NINST][4];  // same, duplicated f32x2
static __device__ double       g_var[BATCH];
static __device__ double       g_lov[BATCH];
static __device__ unsigned int g_P[BATCH];
static __device__ ull          g_chunksum[BATCH][NCHUNK];
static __device__ ull          g_chunkpre[BATCH][NCHUNK];
static __device__ int          g_lab64;

// ---------------------------------------------------------------- packed f32x2 helpers
__device__ __forceinline__ ull fma2(ull a, ull b, ull c) {
    ull d; asm("fma.rn.f32x2 %0, %1, %2, %3;" : "=l"(d) : "l"(a), "l"(b), "l"(c)); return d;
}
__device__ __forceinline__ ull mul2(ull a, ull b) {
    ull d; asm("mul.rn.f32x2 %0, %1, %2;" : "=l"(d) : "l"(a), "l"(b)); return d;
}
__device__ __forceinline__ ull dupf(float f) {
    unsigned u = __float_as_uint(f); return ((ull)u << 32) | u;
}

// ---------------------------------------------------------------- label dtype sniff
__global__ void k_detect(const int* __restrict__ lab32) {
    __shared__ int s_or;
    if (threadIdx.x == 0) s_or = 0;
    __syncthreads();
    int v = lab32[2 * threadIdx.x + 1];
    #pragma unroll
    for (int o = 16; o; o >>= 1) v |= __shfl_down_sync(0xffffffffu, v, o);
    if ((threadIdx.x & 31) == 0) atomicOr(&s_or, v);
    __syncthreads();
    if (threadIdx.x == 0) g_lab64 = (s_or == 0) ? 1 : 0;
}
__device__ __forceinline__ int load_lab(const int* __restrict__ lab32, int idx, int f64) {
    return lab32[f64 ? (idx << 1) : idx];
}

// ---------------------------------------------------------------- zero
__global__ void k_zero() {
    size_t stride = (size_t)gridDim.x * blockDim.x;
    size_t i = (size_t)blockIdx.x * blockDim.x + threadIdx.x;
    ull* th = (ull*)&g_thist[0][0];
    const size_t nt = (size_t)BATCH * NBT / 2;
    for (size_t k = i; k < nt; k += stride) th[k] = 0ULL;
    ull* eh = &g_hist[0][0];
    const size_t ne = (size_t)BATCH * NBE;
    for (size_t k = i; k < ne; k += stride) eh[k] = 0ULL;
    if (i < BATCH * NINST * 4) (&g_sum[0][0][0])[i] = 0.0;
    if (i < BATCH * NINST)     (&g_cnt[0][0])[i] = 0u;
    if (i < BATCH)             { g_var[i] = 0.0; g_lov[i] = 0.0; }
}

// ---------------------------------------------------------------- per-instance stats (4 px/thread)
__global__ void k_stats(const float* __restrict__ emb,
                        const float* __restrict__ sig,
                        const int* __restrict__ lab32) {
    int b = blockIdx.y;
    int base = blockIdx.x * 1024;
    __shared__ float s_sx[NINST], s_sy[NINST], s_ss[NINST], s_ss2[NINST];
    __shared__ unsigned int s_c[NINST];
    if (threadIdx.x < NINST) {
        s_sx[threadIdx.x] = 0.f; s_sy[threadIdx.x] = 0.f;
        s_ss[threadIdx.x] = 0.f; s_ss2[threadIdx.x] = 0.f;
        s_c[threadIdx.x] = 0u;
    }
    __syncthreads();
    int f64 = g_lab64;
    #pragma unroll
    for (int k = 0; k < 4; k++) {
        int pix = base + threadIdx.x + k * 256;
        int g = load_lab(lab32, b * HW + pix, f64);
        if (g > 0 && g <= NINST) {
            int n = g - 1;
            float ex = emb[(b * 2 + 0) * HW + pix];
            float ey = emb[(b * 2 + 1) * HW + pix];
            float s  = sig[b * HW + pix];
            atomicAdd(&s_sx[n], ex);
            atomicAdd(&s_sy[n], ey);
            atomicAdd(&s_ss[n], s);
            atomicAdd(&s_ss2[n], s * s);
            atomicAdd(&s_c[n], 1u);
        }
    }
    __syncthreads();
    if (threadIdx.x < NINST) {
        int n = threadIdx.x;
        if (s_c[n]) {
            atomicAdd(&g_sum[b][n][0], (double)s_sx[n]);
            atomicAdd(&g_sum[b][n][1], (double)s_sy[n]);
            atomicAdd(&g_sum[b][n][2], (double)s_ss[n]);
            atomicAdd(&g_sum[b][n][3], (double)s_ss2[n]);
            atomicAdd(&g_cnt[b][n], s_c[n]);
        }
    }
}

// ---------------------------------------------------------------- finalize: build scaled quadratic params
__global__ void k_finalize() {
    int t = threadIdx.x;              // 128 threads: b = warp, n = lane
    int b = t >> 5, n = t & 31;
    double c  = (double)g_cnt[b][n];
    double ic = (c > 0.0) ? (1.0 / c) : 0.0;
    double cx = g_sum[b][n][0] * ic;
    double cy = g_sum[b][n][1] * ic;
    double m  = g_sum[b][n][2] * ic;
    double vp = g_sum[b][n][3] - c * m * m;
    float Af = 0.f, Bxf = 0.f, Byf = 0.f, Cf = 0.f;
    if (m > 0.0) {
        double s14 = 8192.0 / (m * m);      // 0.5/sigma^2 * 2^14
        Af  = (float)s14;
        Bxf = (float)(-2.0 * cx * s14);
        Byf = (float)(-2.0 * cy * s14);
        Cf  = (float)((cx * cx + cy * cy) * s14);
    }
    g_prm[b][n] = make_float4(Bxf, Byf, Af, Cf);
    g_prm2[b][n][0] = dupf(Af);
    g_prm2[b][n][1] = dupf(Bxf);
    g_prm2[b][n][2] = dupf(Byf);
    g_prm2[b][n][3] = dupf(Cf);
    unsigned cc = g_cnt[b][n];
    double icsum = ic;
    #pragma unroll
    for (int o = 16; o; o >>= 1) {
        vp    += __shfl_down_sync(0xffffffffu, vp, o);
        icsum += __shfl_down_sync(0xffffffffu, icsum, o);
        cc    += __shfl_down_sync(0xffffffffu, cc, o);
    }
    if (n == 0) {
        g_var[b] = vp * icsum / (double)NINST;
        g_P[b]   = cc;
    }
}

// ---------------------------------------------------------------- main: all pairs as negatives -> t-hist
__global__ void k_main(const float* __restrict__ emb) {
    int b = blockIdx.y;
    __shared__ ull sp2[NINST][4];
    if (threadIdx.x < NINST) {
        sp2[threadIdx.x][0] = g_prm2[b][threadIdx.x][0];
        sp2[threadIdx.x][1] = g_prm2[b][threadIdx.x][1];
        sp2[threadIdx.x][2] = g_prm2[b][threadIdx.x][2];
        sp2[threadIdx.x][3] = g_prm2[b][threadIdx.x][3];
    }
    __syncthreads();
    int pix0 = (blockIdx.x * blockDim.x + threadIdx.x) * 2;   // 2 pixels/thread
    ull ex2 = *(const ull*)(emb + (size_t)(b * 2 + 0) * HW + pix0);
    ull ey2 = *(const ull*)(emb + (size_t)(b * 2 + 1) * HW + pix0);
    ull q2  = fma2(ex2, ex2, mul2(ey2, ey2));
    unsigned int* hb = g_thist[b];
    #pragma unroll 8
    for (int n = 0; n < NINST; n++) {
        ull A2 = sp2[n][0], Bx2 = sp2[n][1], By2 = sp2[n][2], C2 = sp2[n][3];
        ull t2 = fma2(A2, q2, C2);
        t2 = fma2(By2, ey2, t2);
        t2 = fma2(Bx2, ex2, t2);
        float tlo = __uint_as_float((unsigned)t2);
        float thi = __uint_as_float((unsigned)(t2 >> 32));
        unsigned b0 = min(__float2uint_rz(tlo), (unsigned)(NBT - 1));
        unsigned b1 = min(__float2uint_rz(thi), (unsigned)(NBT - 1));
        atomicAdd(&hb[b0], 1u);
        atomicAdd(&hb[b1], 1u);
    }
}

// ---------------------------------------------------------------- positives: decrement t-hist, add to e-hist
__global__ void k_pos(const float* __restrict__ emb,
                      const int* __restrict__ lab32) {
    int b = blockIdx.y;
    int pix = blockIdx.x * blockDim.x + threadIdx.x;
    int f64 = g_lab64;
    int g = load_lab(lab32, b * HW + pix, f64);
    if (g < 1 || g > NINST) return;
    float4 P = g_prm[b][g - 1];   // Bx, By, A, C
    float ex = emb[(b * 2 + 0) * HW + pix];
    float ey = emb[(b * 2 + 1) * HW + pix];
    float q  = fmaf(ex, ex, ey * ey);
    float t  = fmaf(P.z, q, P.w);
    t = fmaf(P.y, ey, t);
    t = fmaf(P.x, ex, t);
    unsigned bt = min(__float2uint_rz(t), (unsigned)(NBT - 1));
    atomicAdd(&g_thist[b][bt], 0xFFFFFFFFu);        // -1: cancel the false negative
    float p = __expf(t * (-T_INV));
    float e = fmaf(-2.f, p, 2.f);                    // e in [0,2]
    unsigned be = min(__float_as_uint(e) >> 10, EB_MAX);
    atomicAdd(&g_hist[b][be], 1ULL << 32);
}

// ---------------------------------------------------------------- convert t-hist -> e-hist (neg field)
__global__ void k_conv() {
    int b = blockIdx.y;
    int i0 = (blockIdx.x * blockDim.x + threadIdx.x) * 4;
    uint4 c4 = *(const uint4*)&g_thist[b][i0];
    #pragma unroll
    for (int k = 0; k < 4; k++) {
        unsigned c = (&c4.x)[k];
        if (c) {
            float t = ((float)(i0 + k) + 0.5f) * T_INV;
            float e = 2.f * __expf(-t);
            unsigned be = min(__float_as_uint(e) >> 10, EB_MAX);
            atomicAdd(&g_hist[b][be], (ull)c);
        }
    }
}

// ---------------------------------------------------------------- chunk sums over e-hist
__global__ void k_chunksum() {
    int b = blockIdx.y, c = blockIdx.x;
    const ull* hb = g_hist[b] + (size_t)c * CHUNK;
    ull acc = 0;
    for (int i = threadIdx.x; i < CHUNK; i += blockDim.x) acc += hb[i];
    __shared__ ull ss[256];
    ss[threadIdx.x] = acc; __syncthreads();
    for (int o = 128; o; o >>= 1) {
        if (threadIdx.x < o) ss[threadIdx.x] += ss[threadIdx.x + o];
        __syncthreads();
    }
    if (threadIdx.x == 0) g_chunksum[b][c] = ss[0];
}

// ---------------------------------------------------------------- exclusive scan over chunks (descending e)
__global__ void k_scan() {
    int b = blockIdx.x;
    int t = threadIdx.x;               // 512 threads, NCHUNK=257 entries reversed
    __shared__ ull ss[512];
    ull v = (t < NCHUNK) ? g_chunksum[b][NCHUNK - 1 - t] : 0ULL;
    ss[t] = v; __syncthreads();
    for (int o = 1; o < 512; o <<= 1) {
        ull u = (t >= o) ? ss[t - o] : 0ULL;
        __syncthreads();
        ss[t] += u;
        __syncthreads();
    }
    if (t < NCHUNK) g_chunkpre[b][NCHUNK - 1 - t] = ss[t] - v;
}

// ---------------------------------------------------------------- per-bin Lovasz contributions
__global__ void k_loss() {
    const int SEG = CHUNK / 256;   // 16 bins per thread, descending order
    int b = blockIdx.y, c = blockIdx.x;
    int t = threadIdx.x;
    int top = c * CHUNK + CHUNK - t * SEG;
    const ull* hb = g_hist[b];
    ull vals[SEG];
    ull segsum = 0;
    #pragma unroll
    for (int k = 0; k < SEG; k++) { vals[k] = hb[top - 1 - k]; segsum += vals[k]; }

    __shared__ ull ss[256];
    ss[t] = segsum; __syncthreads();
    #pragma unroll
    for (int o = 1; o < 256; o <<= 1) {
        ull u = (t >= o) ? ss[t - o] : 0ULL;
        __syncthreads();
        ss[t] += u;
        __syncthreads();
    }
    ull pref = g_chunkpre[b][c] + (ss[t] - segsum);
    unsigned pp = (unsigned)(pref >> 32);
    unsigned nn = (unsigned)(pref & 0xffffffffu);
    unsigned P  = g_P[b];
    float contrib = 0.f;
    #pragma unroll
    for (int k = 0; k < SEG; k++) {
        ull v = vals[k];
        if (v) {
            unsigned a  = (unsigned)(v >> 32);
            unsigned gn = (unsigned)v;
            unsigned bin = (unsigned)(top - 1 - k);
            float e = __uint_as_float((bin << 10) + 512u);
            e = fminf(e, 2.0f);
            float A   = (float)(P - pp);
            float U1  = (float)(P + nn);
            float U2  = U1 + (float)gn;
            float num = A * (float)gn + (float)a * U1;
            contrib += e * num / (U1 * U2);
            pp += a; nn += gn;
        }
    }
    __shared__ float sc[256];
    sc[t] = contrib; __syncthreads();
    for (int o = 128; o; o >>= 1) {
        if (t < o) sc[t] += sc[t + o];
        __syncthreads();
    }
    if (t == 0) atomicAdd(&g_lov[b], (double)sc[0]);
}

// ---------------------------------------------------------------- final mean
__global__ void k_final(float* __restrict__ out) {
    double acc = 0.0;
    #pragma unroll
    for (int b = 0; b < BATCH; b++) acc += g_lov[b] + g_var[b];
    out[0] = (float)(acc / (double)BATCH);
}

extern "C" void kernel_launch(void* const* d_in, const int* in_sizes, int n_in,
                              void* d_out, int out_size) {
    const float* emb = (const float*)d_in[0];
    const float* sig = (const float*)d_in[1];
    const int* lab32 = (const int*)d_in[2];
    float* out = (float*)d_out;
    (void)in_sizes; (void)n_in; (void)out_size;

    k_detect<<<1, 256>>>(lab32);
    k_zero<<<2048, 1024>>>();
    k_stats<<<dim3(HW / 1024, BATCH), 256>>>(emb, sig, lab32);
    k_finalize<<<1, 128>>>();
    k_main<<<dim3(HW / 512, BATCH), 256>>>(emb);
    k_pos<<<dim3(HW / 256, BATCH), 256>>>(emb, lab32);
    k_conv<<<dim3(NBT / 1024, BATCH), 256>>>();
    k_chunksum<<<dim3(NCHUNK, BATCH), 256>>>();
    k_scan<<<BATCH, 512>>>();
    k_loss<<<dim3(NCHUNK, BATCH), 256>>>();
    k_final<<<1, 1>>>(out);
}

// round 6
// speedup vs baseline: 1.3718x; 1.0129x over previous
#include <cuda_runtime.h>

#define BATCH 4
#define NINST 32
#define HW (512*512)

typedef unsigned long long ull;

// t-histogram: log-spaced bins = float-bits(t) >> 10, t = 0.5*d^2/sigma^2, clamped at t=64
#define TB_MAX 1089536u            // bits(64.0f)>>10 = 0x42800000>>10
#define NBT 1090560                // TB_MAX+1 padded to 1024

// e-histogram: float-bit bins of e in [0,2], >>11 (rel width 2.4e-4), packed pos<<32|neg
#define EB_SHIFT 11
#define EB_HALF 1024u
#define EB_MAX 524288u             // bits(2.0f)>>11
#define CHUNK 4096
#define NCHUNK 129
#define NBE (NCHUNK*CHUNK)         // 528384

static __device__ unsigned int g_thist[BATCH][NBT];
static __device__ ull          g_hist[BATCH][NBE];
static __device__ double       g_sum[BATCH][NINST][4];   // sx, sy, ssig, ssig2
static __device__ unsigned int g_cnt[BATCH][NINST];
static __device__ ull          g_prm2[BATCH][NINST][4];  // A, Bx, By, C duplicated f32x2
static __device__ double       g_var[BATCH];
static __device__ double       g_lov[BATCH];
static __device__ unsigned int g_P[BATCH];
static __device__ ull          g_chunksum[BATCH][NCHUNK];
static __device__ ull          g_chunkpre[BATCH][NCHUNK];
static __device__ int          g_lab64;

// ---------------------------------------------------------------- packed f32x2 helpers
__device__ __forceinline__ ull fma2(ull a, ull b, ull c) {
    ull d; asm("fma.rn.f32x2 %0, %1, %2, %3;" : "=l"(d) : "l"(a), "l"(b), "l"(c)); return d;
}
__device__ __forceinline__ ull mul2(ull a, ull b) {
    ull d; asm("mul.rn.f32x2 %0, %1, %2;" : "=l"(d) : "l"(a), "l"(b)); return d;
}
__device__ __forceinline__ ull dupf(float f) {
    unsigned u = __float_as_uint(f); return ((ull)u << 32) | u;
}
__device__ __forceinline__ float lane(ull v, int hi) {
    return __uint_as_float(hi ? (unsigned)(v >> 32) : (unsigned)v);
}
// t-bin: unsigned bit shift + clamp (identical in vector and scalar paths!)
__device__ __forceinline__ unsigned tbin(unsigned bits) {
    return min(bits >> 10, TB_MAX);
}
// e-bin with sign-safe clamp
__device__ __forceinline__ unsigned ebin(float e) {
    int s = ((int)__float_as_uint(e)) >> EB_SHIFT;
    return (unsigned)min(max(s, 0), (int)EB_MAX);
}

// ---------------------------------------------------------------- label dtype sniff
__global__ void k_detect(const int* __restrict__ lab32) {
    __shared__ int s_or;
    if (threadIdx.x == 0) s_or = 0;
    __syncthreads();
    int v = lab32[2 * threadIdx.x + 1];
    #pragma unroll
    for (int o = 16; o; o >>= 1) v |= __shfl_down_sync(0xffffffffu, v, o);
    if ((threadIdx.x & 31) == 0) atomicOr(&s_or, v);
    __syncthreads();
    if (threadIdx.x == 0) g_lab64 = (s_or == 0) ? 1 : 0;
}
__device__ __forceinline__ int load_lab(const int* __restrict__ lab32, int idx, int f64) {
    return lab32[f64 ? (idx << 1) : idx];
}

// ---------------------------------------------------------------- zero
__global__ void k_zero() {
    size_t stride = (size_t)gridDim.x * blockDim.x;
    size_t i = (size_t)blockIdx.x * blockDim.x + threadIdx.x;
    ull* th = (ull*)&g_thist[0][0];
    const size_t nt = (size_t)BATCH * NBT / 2;
    for (size_t k = i; k < nt; k += stride) th[k] = 0ULL;
    ull* eh = &g_hist[0][0];
    const size_t ne = (size_t)BATCH * NBE;
    for (size_t k = i; k < ne; k += stride) eh[k] = 0ULL;
    if (i < BATCH * NINST * 4) (&g_sum[0][0][0])[i] = 0.0;
    if (i < BATCH * NINST)     (&g_cnt[0][0])[i] = 0u;
    if (i < BATCH)             { g_var[i] = 0.0; g_lov[i] = 0.0; }
}

// ---------------------------------------------------------------- per-instance stats
__global__ void k_stats(const float* __restrict__ emb,
                        const float* __restrict__ sig,
                        const int* __restrict__ lab32) {
    int b = blockIdx.y;
    int base = blockIdx.x * 1024;
    __shared__ float s_sx[NINST], s_sy[NINST], s_ss[NINST], s_ss2[NINST];
    __shared__ unsigned int s_c[NINST];
    if (threadIdx.x < NINST) {
        s_sx[threadIdx.x] = 0.f; s_sy[threadIdx.x] = 0.f;
        s_ss[threadIdx.x] = 0.f; s_ss2[threadIdx.x] = 0.f;
        s_c[threadIdx.x] = 0u;
    }
    __syncthreads();
    int f64 = g_lab64;
    #pragma unroll
    for (int k = 0; k < 4; k++) {
        int pix = base + threadIdx.x + k * 256;
        int g = load_lab(lab32, b * HW + pix, f64);
        if (g > 0 && g <= NINST) {
            int n = g - 1;
            float ex = emb[(b * 2 + 0) * HW + pix];
            float ey = emb[(b * 2 + 1) * HW + pix];
            float s  = sig[b * HW + pix];
            atomicAdd(&s_sx[n], ex);
            atomicAdd(&s_sy[n], ey);
            atomicAdd(&s_ss[n], s);
            atomicAdd(&s_ss2[n], s * s);
            atomicAdd(&s_c[n], 1u);
        }
    }
    __syncthreads();
    if (threadIdx.x < NINST) {
        int n = threadIdx.x;
        if (s_c[n]) {
            atomicAdd(&g_sum[b][n][0], (double)s_sx[n]);
            atomicAdd(&g_sum[b][n][1], (double)s_sy[n]);
            atomicAdd(&g_sum[b][n][2], (double)s_ss[n]);
            atomicAdd(&g_sum[b][n][3], (double)s_ss2[n]);
            atomicAdd(&g_cnt[b][n], s_c[n]);
        }
    }
}

// ---------------------------------------------------------------- finalize: quadratic params (unscaled t)
__global__ void k_finalize() {
    int t = threadIdx.x;              // 128 threads: b = warp, n = lane
    int b = t >> 5, n = t & 31;
    double c  = (double)g_cnt[b][n];
    double ic = (c > 0.0) ? (1.0 / c) : 0.0;
    double cx = g_sum[b][n][0] * ic;
    double cy = g_sum[b][n][1] * ic;
    double m  = g_sum[b][n][2] * ic;
    double vp = g_sum[b][n][3] - c * m * m;
    float Af = 0.f, Bxf = 0.f, Byf = 0.f, Cf = 0.f;
    if (m > 0.0) {
        double A = 0.5 / (m * m);          // t = A*d^2 (unscaled)
        Af  = (float)A;
        Bxf = (float)(-2.0 * cx * A);
        Byf = (float)(-2.0 * cy * A);
        Cf  = (float)((cx * cx + cy * cy) * A);
    }
    g_prm2[b][n][0] = dupf(Af);
    g_prm2[b][n][1] = dupf(Bxf);
    g_prm2[b][n][2] = dupf(Byf);
    g_prm2[b][n][3] = dupf(Cf);
    unsigned cc = g_cnt[b][n];
    double icsum = ic;
    #pragma unroll
    for (int o = 16; o; o >>= 1) {
        vp    += __shfl_down_sync(0xffffffffu, vp, o);
        icsum += __shfl_down_sync(0xffffffffu, icsum, o);
        cc    += __shfl_down_sync(0xffffffffu, cc, o);
    }
    if (n == 0) {
        g_var[b] = vp * icsum / (double)NINST;
        g_P[b]   = cc;
    }
}

// ---------------------------------------------------------------- main: 4 px/thread, all pairs -> t-hist,
//                                                                  positives fixed up inline
__global__ void k_main(const float* __restrict__ emb,
                       const int* __restrict__ lab32) {
    int b = blockIdx.y;
    __shared__ ull sp2[NINST][4];
    if (threadIdx.x < NINST * 2) {
        ((ull*)sp2)[threadIdx.x * 2 + 0] = ((ull*)g_prm2[b])[threadIdx.x * 2 + 0];
        ((ull*)sp2)[threadIdx.x * 2 + 1] = ((ull*)g_prm2[b])[threadIdx.x * 2 + 1];
    }
    __syncthreads();
    int pix0 = (blockIdx.x * blockDim.x + threadIdx.x) * 4;
    const ulonglong2 exv = *(const ulonglong2*)(emb + (size_t)(b * 2 + 0) * HW + pix0);
    const ulonglong2 eyv = *(const ulonglong2*)(emb + (size_t)(b * 2 + 1) * HW + pix0);
    ull exa = exv.x, exb = exv.y, eya = eyv.x, eyb = eyv.y;
    ull qa = fma2(exa, exa, mul2(eya, eya));
    ull qb = fma2(exb, exb, mul2(eyb, eyb));
    unsigned int* hb = g_thist[b];
    #pragma unroll 8
    for (int n = 0; n < NINST; n++) {
        ull A2 = sp2[n][0], Bx2 = sp2[n][1], By2 = sp2[n][2], C2 = sp2[n][3];
        ull ta = fma2(Bx2, exa, fma2(By2, eya, fma2(A2, qa, C2)));
        ull tb = fma2(Bx2, exb, fma2(By2, eyb, fma2(A2, qb, C2)));
        atomicAdd(&hb[tbin((unsigned)ta)], 1u);
        atomicAdd(&hb[tbin((unsigned)(ta >> 32))], 1u);
        atomicAdd(&hb[tbin((unsigned)tb)], 1u);
        atomicAdd(&hb[tbin((unsigned)(tb >> 32))], 1u);
    }
    // positive fixups (one pair per pixel, ~97% of pixels)
    int f64 = g_lab64;
    #pragma unroll
    for (int k = 0; k < 4; k++) {
        int g = load_lab(lab32, b * HW + pix0 + k, f64);
        if (g > 0 && g <= NINST) {
            int n = g - 1;
            float A  = lane(sp2[n][0], 0), Bx = lane(sp2[n][1], 0);
            float By = lane(sp2[n][2], 0), C  = lane(sp2[n][3], 0);
            float ex = lane(k < 2 ? exa : exb, k & 1);
            float ey = lane(k < 2 ? eya : eyb, k & 1);
            float q  = fmaf(ex, ex, ey * ey);           // bit-identical to f32x2 lane
            float t  = fmaf(Bx, ex, fmaf(By, ey, fmaf(A, q, C)));
            atomicAdd(&hb[tbin(__float_as_uint(t))], 0xFFFFFFFFu);  // cancel false negative
            float p = __expf(-t);
            float e = fmaf(-2.f, p, 2.f);
            atomicAdd(&g_hist[b][ebin(e)], 1ULL << 32);
        }
    }
}

// ---------------------------------------------------------------- convert t-hist -> e-hist (neg field)
__global__ void k_conv() {
    int b = blockIdx.y;
    int i0 = (blockIdx.x * blockDim.x + threadIdx.x) * 4;
    uint4 c4 = *(const uint4*)&g_thist[b][i0];
    #pragma unroll
    for (int k = 0; k < 4; k++) {
        unsigned c = (&c4.x)[k];
        if (c) {
            float t = __uint_as_float(((unsigned)(i0 + k) << 10) + 512u);  // bin-center t
            float e = 2.f * __expf(-t);
            atomicAdd(&g_hist[b][ebin(e)], (ull)c);
        }
    }
}

// ---------------------------------------------------------------- chunk sums over e-hist
__global__ void k_chunksum() {
    int b = blockIdx.y, c = blockIdx.x;
    const ull* hb = g_hist[b] + (size_t)c * CHUNK;
    ull acc = 0;
    for (int i = threadIdx.x; i < CHUNK; i += blockDim.x) acc += hb[i];
    __shared__ ull ss[256];
    ss[threadIdx.x] = acc; __syncthreads();
    for (int o = 128; o; o >>= 1) {
        if (threadIdx.x < o) ss[threadIdx.x] += ss[threadIdx.x + o];
        __syncthreads();
    }
    if (threadIdx.x == 0) g_chunksum[b][c] = ss[0];
}

// ---------------------------------------------------------------- exclusive scan over chunks (descending e)
__global__ void k_scan() {
    int b = blockIdx.x;
    int t = threadIdx.x;               // 256 threads, NCHUNK=129 entries reversed
    __shared__ ull ss[256];
    ull v = (t < NCHUNK) ? g_chunksum[b][NCHUNK - 1 - t] : 0ULL;
    ss[t] = v; __syncthreads();
    for (int o = 1; o < 256; o <<= 1) {
        ull u = (t >= o) ? ss[t - o] : 0ULL;
        __syncthreads();
        ss[t] += u;
        __syncthreads();
    }
    if (t < NCHUNK) g_chunkpre[b][NCHUNK - 1 - t] = ss[t] - v;
}

// ---------------------------------------------------------------- per-bin Lovasz contributions
__global__ void k_loss() {
    const int SEG = CHUNK / 256;   // 16 bins per thread, descending order
    int b = blockIdx.y, c = blockIdx.x;
    int t = threadIdx.x;
    int top = c * CHUNK + CHUNK - t * SEG;
    const ull* hb = g_hist[b];
    ull vals[SEG];
    ull segsum = 0;
    #pragma unroll
    for (int k = 0; k < SEG; k++) { vals[k] = hb[top - 1 - k]; segsum += vals[k]; }

    __shared__ ull ss[256];
    ss[t] = segsum; __syncthreads();
    #pragma unroll
    for (int o = 1; o < 256; o <<= 1) {
        ull u = (t >= o) ? ss[t - o] : 0ULL;
        __syncthreads();
        ss[t] += u;
        __syncthreads();
    }
    ull pref = g_chunkpre[b][c] + (ss[t] - segsum);
    unsigned pp = (unsigned)(pref >> 32);
    unsigned nn = (unsigned)(pref & 0xffffffffu);
    unsigned P  = g_P[b];
    float contrib = 0.f;
    #pragma unroll
    for (int k = 0; k < SEG; k++) {
        ull v = vals[k];
        if (v) {
            unsigned a  = (unsigned)(v >> 32);
            unsigned gn = (unsigned)v;
            unsigned bin = (unsigned)(top - 1 - k);
            float e = __uint_as_float((bin << EB_SHIFT) + EB_HALF);
            e = fminf(e, 2.0f);
            float A   = (float)(P - pp);
            float U1  = (float)(P + nn);
            float U2  = U1 + (float)gn;
            float num = A * (float)gn + (float)a * U1;
            contrib += e * num / (U1 * U2);
            pp += a; nn += gn;
        }
    }
    __shared__ float sc[256];
    sc[t] = contrib; __syncthreads();
    for (int o = 128; o; o >>= 1) {
        if (t < o) sc[t] += sc[t + o];
        __syncthreads();
    }
    if (t == 0) atomicAdd(&g_lov[b], (double)sc[0]);
}

// ---------------------------------------------------------------- final mean
__global__ void k_final(float* __restrict__ out) {
    double acc = 0.0;
    #pragma unroll
    for (int b = 0; b < BATCH; b++) acc += g_lov[b] + g_var[b];
    out[0] = (float)(acc / (double)BATCH);
}

extern "C" void kernel_launch(void* const* d_in, const int* in_sizes, int n_in,
                              void* d_out, int out_size) {
    const float* emb = (const float*)d_in[0];
    const float* sig = (const float*)d_in[1];
    const int* lab32 = (const int*)d_in[2];
    float* out = (float*)d_out;
    (void)in_sizes; (void)n_in; (void)out_size;

    k_detect<<<1, 256>>>(lab32);
    k_zero<<<2048, 1024>>>();
    k_stats<<<dim3(HW / 1024, BATCH), 256>>>(emb, sig, lab32);
    k_finalize<<<1, 128>>>();
    k_main<<<dim3(HW / 1024, BATCH), 256>>>(emb, lab32);
    k_conv<<<dim3(NBT / 1024, BATCH), 256>>>();
    k_chunksum<<<dim3(NCHUNK, BATCH), 256>>>();
    k_scan<<<BATCH, 256>>>();
    k_loss<<<dim3(NCHUNK, BATCH), 256>>>();
    k_final<<<1, 1>>>(out);
}